// round 11
// baseline (speedup 1.0000x reference)
#include <cuda_runtime.h>
#include <cuda_bf16.h>

#define G   16
#define Bsz 2
#define C   256
#define Cg  16
#define HW  576
#define AC  6400
#define EPSV 1e-5f

// -------- device scratch --------
__device__ float g_h1[G * Bsz * C * HW];   // 18.9 MB
__device__ float g_pooled[G * Bsz * AC];
__device__ float g_aff[G * Bsz * G];

// ---------- bf16 helpers ----------
__device__ __forceinline__ unsigned int f2bf2(float lo, float hi) {
    unsigned int r;
    asm("cvt.rn.bf16x2.f32 %0, %1, %2;" : "=r"(r) : "f"(hi), "f"(lo));
    return r;
}
__device__ __forceinline__ float bfhi(float f) {
    return __bfloat162float(__float2bfloat16(f));
}
__device__ __forceinline__ void mma_bf16(
    float& d0, float& d1, float& d2, float& d3,
    unsigned int a0, unsigned int a1, unsigned int a2, unsigned int a3,
    unsigned int b0, unsigned int b1)
{
    asm("mma.sync.aligned.m16n8k16.row.col.f32.bf16.bf16.f32 "
        "{%0,%1,%2,%3}, {%4,%5,%6,%7}, {%8,%9}, {%0,%1,%2,%3};"
        : "+f"(d0), "+f"(d1), "+f"(d2), "+f"(d3)
        : "r"(a0), "r"(a1), "r"(a2), "r"(a3), "r"(b0), "r"(b1));
}

// ---------- packed f32x2 helpers ----------
__device__ __forceinline__ unsigned long long pack2(float x, float y) {
    unsigned long long r;
    asm("mov.b64 %0, {%1,%2};" : "=l"(r) : "f"(x), "f"(y));
    return r;
}
__device__ __forceinline__ float2 unpack2(unsigned long long v) {
    float2 f;
    asm("mov.b64 {%0,%1}, %2;" : "=f"(f.x), "=f"(f.y) : "l"(v));
    return f;
}
__device__ __forceinline__ unsigned long long add2(unsigned long long a,
                                                   unsigned long long b) {
    unsigned long long d;
    asm("add.rn.f32x2 %0, %1, %2;" : "=l"(d) : "l"(a), "l"(b));
    return d;
}
#define ABS2MASK 0x7FFFFFFF7FFFFFFFULL

// ============================================================
// Kernel 1 (tensor cores): grouped 3x3 conv + BN + ReLU -> g_h1
// Implicit GEMM over K = 9 taps x 16 ci, bf16 hi/lo split.
// grid (k=16, b=2, g=16), 288 threads = 9 warps. Dynamic smem 52.9 KB.
// ============================================================
#define BPITCH 680
#define K1_DYN ((2*8*BPITCH + 2*9*128 + 32) * 4)

__global__ __launch_bounds__(288) void k1_tc(
    const float* __restrict__ x,
    const float* __restrict__ W1,
    const float* __restrict__ g1, const float* __restrict__ b1,
    const float* __restrict__ m1, const float* __restrict__ v1)
{
    const int k = blockIdx.x, b = blockIdx.y, g = blockIdx.z;
    extern __shared__ unsigned int dyn[];
    unsigned int* Bh = dyn;
    unsigned int* Bl = Bh + 8 * BPITCH;
    unsigned int* Ah = Bl + 8 * BPITCH;
    unsigned int* Al = Ah + 9 * 128;
    float* scb = reinterpret_cast<float*>(Al + 9 * 128);

    const int tid = threadIdx.x;

    for (int i = tid; i < 8 * BPITCH; i += 288) { Bh[i] = 0u; Bl[i] = 0u; }

    const float* wsrc = W1 + (g * 256 + k * 16) * 144;
    for (int i = tid; i < 1152; i += 288) {
        int t = i / 128, rem = i % 128, p = rem / 16, r = rem % 16;
        float f0 = wsrc[r * 144 + (2 * p) * 9 + t];
        float f1 = wsrc[r * 144 + (2 * p + 1) * 9 + t];
        float h0 = bfhi(f0), h1 = bfhi(f1);
        Ah[i] = f2bf2(h0, h1);
        Al[i] = f2bf2(f0 - h0, f1 - h1);
    }
    if (tid < 16) {
        const int ch = g * 256 + k * 16 + tid;
        float sc = g1[ch] * rsqrtf(v1[ch] + EPSV);
        scb[tid] = sc;
        scb[16 + tid] = b1[ch] - m1[ch] * sc;
    }
    __syncthreads();

    const float* xs = x + (b * 256 + k * 16) * 576;
    for (int i = tid; i < 8 * 576; i += 288) {
        int q = i / 576, pos = i % 576;
        int y = pos / 24, xx = pos % 24;
        float f0 = xs[(2 * q) * 576 + pos];
        float f1 = xs[(2 * q + 1) * 576 + pos];
        float h0 = bfhi(f0), h1 = bfhi(f1);
        int pp = q * BPITCH + (y + 1) * 26 + (xx + 1);
        Bh[pp] = f2bf2(h0, h1);
        Bl[pp] = f2bf2(f0 - h0, f1 - h1);
    }
    __syncthreads();

    const int w    = tid >> 5;
    const int lane = tid & 31;
    const int gq   = lane >> 2;
    const int tg   = lane & 3;

    float d[8][4];
#pragma unroll
    for (int j = 0; j < 8; ++j)
#pragma unroll
        for (int c = 0; c < 4; ++c) d[j][c] = 0.f;

#pragma unroll
    for (int t = 0; t < 9; ++t) {
        const int base = t * 128;
        unsigned int ah0 = Ah[base + tg * 16 + gq];
        unsigned int ah1 = Ah[base + tg * 16 + gq + 8];
        unsigned int ah2 = Ah[base + (tg + 4) * 16 + gq];
        unsigned int ah3 = Ah[base + (tg + 4) * 16 + gq + 8];
        unsigned int al0 = Al[base + tg * 16 + gq];
        unsigned int al1 = Al[base + tg * 16 + gq + 8];
        unsigned int al2 = Al[base + (tg + 4) * 16 + gq];
        unsigned int al3 = Al[base + (tg + 4) * 16 + gq + 8];
        const int ty = t / 3, tx = t % 3;

#pragma unroll
        for (int j = 0; j < 8; ++j) {
            const int nt = w * 8 + j;
            const int y = nt / 3, x0 = (nt % 3) * 8;
            const int pp = (y + ty) * 26 + x0 + gq + tx;
            unsigned int b0h = Bh[tg * BPITCH + pp];
            unsigned int b1h = Bh[(tg + 4) * BPITCH + pp];
            unsigned int b0l = Bl[tg * BPITCH + pp];
            unsigned int b1l = Bl[(tg + 4) * BPITCH + pp];
            mma_bf16(d[j][0], d[j][1], d[j][2], d[j][3], al0, al1, al2, al3, b0h, b1h);
            mma_bf16(d[j][0], d[j][1], d[j][2], d[j][3], ah0, ah1, ah2, ah3, b0l, b1l);
            mma_bf16(d[j][0], d[j][1], d[j][2], d[j][3], ah0, ah1, ah2, ah3, b0h, b1h);
        }
    }

    const float sc0 = scb[gq],     bi0 = scb[16 + gq];
    const float sc1 = scb[gq + 8], bi1 = scb[24 + gq];
    float* dst = g_h1 + ((g * 2 + b) * 256 + k * 16) * 576;
#pragma unroll
    for (int j = 0; j < 8; ++j) {
        const int nt = w * 8 + j;
        const int pos = nt * 8 + 2 * tg;
        float2 v0, v1;
        v0.x = fmaxf(fmaf(d[j][0], sc0, bi0), 0.f);
        v0.y = fmaxf(fmaf(d[j][1], sc0, bi0), 0.f);
        v1.x = fmaxf(fmaf(d[j][2], sc1, bi1), 0.f);
        v1.y = fmaxf(fmaf(d[j][3], sc1, bi1), 0.f);
        *reinterpret_cast<float2*>(dst + gq * 576 + pos)       = v0;
        *reinterpret_cast<float2*>(dst + (gq + 8) * 576 + pos) = v1;
    }
}

// ============================================================
// Kernel 2 (tensor cores): per (g,b,k) GEMM + BN + ReLU + avg-pool.
// Epilogue: sum relu(y) = (Sum y + Sum|y|)/2; Sum y exact from hsum;
// Sum|y| accumulated as PACKED f32x2 adds with abs via 64-bit AND on
// the ALU pipe (FMA-pipe ops per (nt,e): 8 -> 4).
// 13 warps; warp w processes strips w and w+13 together.
// ============================================================
__global__ __launch_bounds__(416) void k2_tc(
    const float* __restrict__ W2,
    const float* __restrict__ g2, const float* __restrict__ b2,
    const float* __restrict__ m2, const float* __restrict__ v2)
{
    const int k = blockIdx.x, b = blockIdx.y, g = blockIdx.z;

    __shared__ unsigned int Bh[8][584];   // pitch 584 (mod 32 == 8)
    __shared__ unsigned int Bl[8][584];
    __shared__ float part[16][48];
    __shared__ float hsum[16];

    const int tid = threadIdx.x;
    const float* src = g_h1 + ((g * 2 + b) * 256 + k * 16) * 576;

    if (tid < 384) {
        const int q = tid / 48, r = tid % 48;
        const float* s0p = src + (2 * q) * 576;
        const float* s1p = src + (2 * q + 1) * 576;
        float a0 = 0.f, a1 = 0.f;
#pragma unroll
        for (int n = 0; n < 12; ++n) {
            const int pos = r + 48 * n;
            float f0 = s0p[pos], f1 = s1p[pos];
            float h0 = bfhi(f0), h1 = bfhi(f1);
            Bh[q][pos] = f2bf2(h0, h1);
            Bl[q][pos] = f2bf2(f0 - h0, f1 - h1);
            a0 += f0; a1 += f1;
        }
        part[2 * q][r] = a0;
        part[2 * q + 1][r] = a1;
    }
    __syncthreads();
    if (tid < 16) {
        float s = 0.f;
#pragma unroll
        for (int j = 0; j < 48; ++j) s += part[tid][j];
        hsum[tid] = s;
    }
    __syncthreads();

    const int w    = tid >> 5;
    const int lane = tid & 31;
    const int gq   = lane >> 2;
    const int tg   = lane & 3;

    const int s0i = w;
    const int s1raw = w + 13;
    const int s1i = (s1raw < 25) ? s1raw : s0i;

    const float hs0 = hsum[2 * tg];
    const float hs1 = hsum[2 * tg + 1];
    const float hs2 = hsum[2 * tg + 8];
    const float hs3 = hsum[2 * tg + 9];

    unsigned int ah[2][4], al[2][4];
    float sc[2][2], bi[2][2], Sd[2][2];
    unsigned long long bip0p[2], bip1p[2];
    int acB[2];
    const int ss[2] = { s0i, s1i };
#pragma unroll
    for (int e = 0; e < 2; ++e) {
        acB[e] = k * 400 + ss[e] * 16;
        const int pi0 = g * 6400 + acB[e] + gq;
        const int pi1 = pi0 + 8;
        const float2* A0 = reinterpret_cast<const float2*>(W2 + (size_t)pi0 * 16);
        const float2* A1 = reinterpret_cast<const float2*>(W2 + (size_t)pi1 * 16);
        float2 p00 = A0[tg], p02 = A0[tg + 4];
        float2 p10 = A1[tg], p12 = A1[tg + 4];
        ah[e][0] = f2bf2(bfhi(p00.x), bfhi(p00.y));
        ah[e][1] = f2bf2(bfhi(p10.x), bfhi(p10.y));
        ah[e][2] = f2bf2(bfhi(p02.x), bfhi(p02.y));
        ah[e][3] = f2bf2(bfhi(p12.x), bfhi(p12.y));
        al[e][0] = f2bf2(p00.x - bfhi(p00.x), p00.y - bfhi(p00.y));
        al[e][1] = f2bf2(p10.x - bfhi(p10.x), p10.y - bfhi(p10.y));
        al[e][2] = f2bf2(p02.x - bfhi(p02.x), p02.y - bfhi(p02.y));
        al[e][3] = f2bf2(p12.x - bfhi(p12.x), p12.y - bfhi(p12.y));
        sc[e][0] = g2[pi0] * rsqrtf(v2[pi0] + EPSV);
        bi[e][0] = b2[pi0] - m2[pi0] * sc[e][0];
        sc[e][1] = g2[pi1] * rsqrtf(v2[pi1] + EPSV);
        bi[e][1] = b2[pi1] - m2[pi1] * sc[e][1];
        float q0 = bi[e][0] / sc[e][0];
        float q1 = bi[e][1] / sc[e][1];
        bip0p[e] = pack2(q0, q0);   // for d0,d1 (row gq)
        bip1p[e] = pack2(q1, q1);   // for d2,d3 (row gq+8)
        Sd[e][0] = p00.x * hs0 + p00.y * hs1 + p02.x * hs2 + p02.y * hs3;
        Sd[e][1] = p10.x * hs0 + p10.y * hs1 + p12.x * hs2 + p12.y * hs3;
    }

    // packed |.| accumulators
    unsigned long long T01[2] = {0ull, 0ull};
    unsigned long long T23[2] = {0ull, 0ull};

#pragma unroll 4
    for (int nt = 0; nt < 72; ++nt) {
        const int pos = nt * 8 + gq;
        unsigned int b0h = Bh[tg][pos];
        unsigned int b1h = Bh[tg + 4][pos];
        unsigned int b0l = Bl[tg][pos];
        unsigned int b1l = Bl[tg + 4][pos];

#pragma unroll
        for (int e = 0; e < 2; ++e) {
            float d0 = 0.f, d1 = 0.f, d2 = 0.f, d3 = 0.f;
            mma_bf16(d0, d1, d2, d3, al[e][0], al[e][1], al[e][2], al[e][3], b0h, b1h);
            mma_bf16(d0, d1, d2, d3, ah[e][0], ah[e][1], ah[e][2], ah[e][3], b0l, b1l);
            mma_bf16(d0, d1, d2, d3, ah[e][0], ah[e][1], ah[e][2], ah[e][3], b0h, b1h);
            // packed epilogue: t = d + bi/sc (f32x2), abs via ALU-pipe AND
            unsigned long long t01 = add2(pack2(d0, d1), bip0p[e]);
            unsigned long long t23 = add2(pack2(d2, d3), bip1p[e]);
            T01[e] = add2(T01[e], t01 & ABS2MASK);
            T23[e] = add2(T23[e], t23 & ABS2MASK);
        }
    }

#pragma unroll
    for (int e = 0; e < 2; ++e) {
        float2 f01 = unpack2(T01[e]);
        float2 f23 = unpack2(T23[e]);
        float t0 = f01.x + f01.y;
        float t1 = f23.x + f23.y;
        float s0 = Sd[e][0], s1 = Sd[e][1];
        t0 += __shfl_xor_sync(0xffffffffu, t0, 1);
        t0 += __shfl_xor_sync(0xffffffffu, t0, 2);
        t1 += __shfl_xor_sync(0xffffffffu, t1, 1);
        t1 += __shfl_xor_sync(0xffffffffu, t1, 2);
        s0 += __shfl_xor_sync(0xffffffffu, s0, 1);
        s0 += __shfl_xor_sync(0xffffffffu, s0, 2);
        s1 += __shfl_xor_sync(0xffffffffu, s1, 1);
        s1 += __shfl_xor_sync(0xffffffffu, s1, 2);
        if (tg == 0) {
            float* dst = g_pooled + (g * 2 + b) * 6400;
            float S0 = fmaf(sc[e][0], s0, 576.f * bi[e][0]);
            float R0 = 0.5f * fmaf(sc[e][0], t0, S0);
            float S1 = fmaf(sc[e][1], s1, 576.f * bi[e][1]);
            float R1 = 0.5f * fmaf(sc[e][1], t1, S1);
            dst[acB[e] + gq]     = (R0 + 100.f * fmaxf(bi[e][0], 0.f)) * (1.f / 676.f);
            dst[acB[e] + gq + 8] = (R1 + 100.f * fmaxf(bi[e][1], 0.f)) * (1.f / 676.f);
        }
    }
}

// ============================================================
// Kernel 3: affinity rows. grid 32 = (i*2+b), 512 thr = 16 warps
// ============================================================
__global__ __launch_bounds__(512) void k3_aff()
{
    const int ib = blockIdx.x;
    const int i = ib >> 1;
    const int wrp = threadIdx.x >> 5, lane = threadIdx.x & 31;
    const float* base = g_pooled + ib * 6400;
    const float* pa = base + i * 400;
    const float* pb = base + wrp * 400;
    float s = 0.f;
    for (int m = lane; m < 400; m += 32) s += pa[m] * pb[m];
#pragma unroll
    for (int o = 16; o; o >>= 1) s += __shfl_xor_sync(0xffffffffu, s, o);
    if (lane == 0) g_aff[ib * 16 + wrp] = s * (1.f / 16.f);
}

// ============================================================
// Kernel 4: z = aff . h1 -> out, float4 vectorized
// grid (cg=16, q=2, i=16), 144 threads, each owns 4 positions
// ============================================================
__global__ __launch_bounds__(144) void k4_out(float* __restrict__ out)
{
    const int cg = blockIdx.x, q = blockIdx.y, i = blockIdx.z;
    __shared__ float a0[16], a1[16];
    const int tid = threadIdx.x;
    if (tid < 16)      a0[tid]      = g_aff[(i * 2 + 0) * 16 + tid];
    else if (tid < 32) a1[tid - 16] = g_aff[(i * 2 + 1) * 16 + (tid - 16)];
    __syncthreads();

    const float4* hb = reinterpret_cast<const float4*>(
        g_h1 + ((i * 2 + q) * 256 + cg) * 576) + tid;
    float4 acc0 = {0.f, 0.f, 0.f, 0.f};
    float4 acc1 = {0.f, 0.f, 0.f, 0.f};
#pragma unroll
    for (int kk = 0; kk < 16; ++kk) {
        float4 hv = hb[kk * 16 * 144];
        float w0 = a0[kk], w1 = a1[kk];
        acc0.x = fmaf(w0, hv.x, acc0.x); acc0.y = fmaf(w0, hv.y, acc0.y);
        acc0.z = fmaf(w0, hv.z, acc0.z); acc0.w = fmaf(w0, hv.w, acc0.w);
        acc1.x = fmaf(w1, hv.x, acc1.x); acc1.y = fmaf(w1, hv.y, acc1.y);
        acc1.z = fmaf(w1, hv.z, acc1.z); acc1.w = fmaf(w1, hv.w, acc1.w);
    }
    const int ch = (i * 2 + q) * 16 + cg;
    float4* o0 = reinterpret_cast<float4*>(out + (0 * 512 + ch) * 576) + tid;
    float4* o1 = reinterpret_cast<float4*>(out + (1 * 512 + ch) * 576) + tid;
    *o0 = acc0;
    *o1 = acc1;
}

// ============================================================
extern "C" void kernel_launch(void* const* d_in, const int* in_sizes, int n_in,
                              void* d_out, int out_size)
{
    const float* x  = (const float*)d_in[0];
    const float* W1 = (const float*)d_in[1];
    const float* g1 = (const float*)d_in[2];
    const float* b1 = (const float*)d_in[3];
    const float* m1 = (const float*)d_in[4];
    const float* v1 = (const float*)d_in[5];
    const float* W2 = (const float*)d_in[6];
    const float* g2 = (const float*)d_in[7];
    const float* b2 = (const float*)d_in[8];
    const float* m2 = (const float*)d_in[9];
    const float* v2 = (const float*)d_in[10];
    float* out = (float*)d_out;

    cudaFuncSetAttribute(k1_tc, cudaFuncAttributeMaxDynamicSharedMemorySize, K1_DYN);

    dim3 grid(16, 2, 16);
    k1_tc <<<grid, 288, K1_DYN>>>(x, W1, g1, b1, m1, v1);
    k2_tc <<<grid, 416>>>(W2, g2, b2, m2, v2);
    k3_aff<<<32, 512>>>();
    k4_out<<<grid, 144>>>(out);
}

// round 12
// speedup vs baseline: 1.2646x; 1.2646x over previous
#include <cuda_runtime.h>
#include <cuda_bf16.h>
#include <cuda_fp16.h>

#define G   16
#define Bsz 2
#define C   256
#define Cg  16
#define HW  576
#define AC  6400
#define EPSV 1e-5f

// -------- device scratch --------
__device__ float g_h1[G * Bsz * C * HW];   // 18.9 MB
__device__ float g_pooled[G * Bsz * AC];
__device__ float g_aff[G * Bsz * G];

// ---------- fp16 helpers ----------
__device__ __forceinline__ unsigned int f2h2(float lo, float hi) {
    __half2 h = __floats2half2_rn(lo, hi);
    return *reinterpret_cast<unsigned int*>(&h);
}
__device__ __forceinline__ float hhi(float f) {   // value after fp16 rounding
    return __half2float(__float2half_rn(f));
}
__device__ __forceinline__ void mma_f16(
    float& d0, float& d1, float& d2, float& d3,
    unsigned int a0, unsigned int a1, unsigned int a2, unsigned int a3,
    unsigned int b0, unsigned int b1)
{
    asm("mma.sync.aligned.m16n8k16.row.col.f32.f16.f16.f32 "
        "{%0,%1,%2,%3}, {%4,%5,%6,%7}, {%8,%9}, {%0,%1,%2,%3};"
        : "+f"(d0), "+f"(d1), "+f"(d2), "+f"(d3)
        : "r"(a0), "r"(a1), "r"(a2), "r"(a3), "r"(b0), "r"(b1));
}

// ============================================================
// Kernel 1 (tensor cores): grouped 3x3 conv + BN + ReLU -> g_h1
// Implicit GEMM over K = 9 taps x 16 ci, fp16 with 2-term A split.
// grid (k=16, b=2, g=16), 288 threads = 9 warps. Dynamic smem ~31 KB.
// ============================================================
#define BPITCH 680
#define K1_DYN ((8*BPITCH + 2*9*128 + 32) * 4)

__global__ __launch_bounds__(288) void k1_tc(
    const float* __restrict__ x,
    const float* __restrict__ W1,
    const float* __restrict__ g1, const float* __restrict__ b1,
    const float* __restrict__ m1, const float* __restrict__ v1)
{
    const int k = blockIdx.x, b = blockIdx.y, g = blockIdx.z;
    extern __shared__ unsigned int dyn[];
    unsigned int* Bv = dyn;                 // 8 ci-pairs x BPITCH (fp16x2)
    unsigned int* Ah = Bv + 8 * BPITCH;     // [tap9][pair8][row16]
    unsigned int* Al = Ah + 9 * 128;
    float* scb = reinterpret_cast<float*>(Al + 9 * 128);

    const int tid = threadIdx.x;

    for (int i = tid; i < 8 * BPITCH; i += 288) Bv[i] = 0u;

    const float* wsrc = W1 + (g * 256 + k * 16) * 144;  // [co16][ci16][tap9]
    for (int i = tid; i < 1152; i += 288) {
        int t = i / 128, rem = i % 128, p = rem / 16, r = rem % 16;
        float f0 = wsrc[r * 144 + (2 * p) * 9 + t];
        float f1 = wsrc[r * 144 + (2 * p + 1) * 9 + t];
        Ah[i] = f2h2(hhi(f0), hhi(f1));
        Al[i] = f2h2(f0 - hhi(f0), f1 - hhi(f1));
    }
    if (tid < 16) {
        const int ch = g * 256 + k * 16 + tid;
        float sc = g1[ch] * rsqrtf(v1[ch] + EPSV);
        scb[tid] = sc;
        scb[16 + tid] = b1[ch] - m1[ch] * sc;
    }
    __syncthreads();

    const float* xs = x + (b * 256 + k * 16) * 576;
    for (int i = tid; i < 8 * 576; i += 288) {
        int q = i / 576, pos = i % 576;
        int y = pos / 24, xx = pos % 24;
        float f0 = xs[(2 * q) * 576 + pos];
        float f1 = xs[(2 * q + 1) * 576 + pos];
        Bv[q * BPITCH + (y + 1) * 26 + (xx + 1)] = f2h2(f0, f1);
    }
    __syncthreads();

    const int w    = tid >> 5;
    const int lane = tid & 31;
    const int gq   = lane >> 2;
    const int tg   = lane & 3;

    float d[8][4];
#pragma unroll
    for (int j = 0; j < 8; ++j)
#pragma unroll
        for (int c = 0; c < 4; ++c) d[j][c] = 0.f;

#pragma unroll
    for (int t = 0; t < 9; ++t) {
        const int base = t * 128;
        unsigned int ah0 = Ah[base + tg * 16 + gq];
        unsigned int ah1 = Ah[base + tg * 16 + gq + 8];
        unsigned int ah2 = Ah[base + (tg + 4) * 16 + gq];
        unsigned int ah3 = Ah[base + (tg + 4) * 16 + gq + 8];
        unsigned int al0 = Al[base + tg * 16 + gq];
        unsigned int al1 = Al[base + tg * 16 + gq + 8];
        unsigned int al2 = Al[base + (tg + 4) * 16 + gq];
        unsigned int al3 = Al[base + (tg + 4) * 16 + gq + 8];
        const int ty = t / 3, tx = t % 3;

#pragma unroll
        for (int j = 0; j < 8; ++j) {
            const int nt = w * 8 + j;
            const int y = nt / 3, x0 = (nt % 3) * 8;
            const int pp = (y + ty) * 26 + x0 + gq + tx;
            unsigned int b0 = Bv[tg * BPITCH + pp];
            unsigned int b1 = Bv[(tg + 4) * BPITCH + pp];
            mma_f16(d[j][0], d[j][1], d[j][2], d[j][3], al0, al1, al2, al3, b0, b1);
            mma_f16(d[j][0], d[j][1], d[j][2], d[j][3], ah0, ah1, ah2, ah3, b0, b1);
        }
    }

    const float sc0 = scb[gq],     bi0 = scb[16 + gq];
    const float sc1 = scb[gq + 8], bi1 = scb[24 + gq];
    float* dst = g_h1 + ((g * 2 + b) * 256 + k * 16) * 576;
#pragma unroll
    for (int j = 0; j < 8; ++j) {
        const int nt = w * 8 + j;
        const int pos = nt * 8 + 2 * tg;
        float2 v0, v1;
        v0.x = fmaxf(fmaf(d[j][0], sc0, bi0), 0.f);
        v0.y = fmaxf(fmaf(d[j][1], sc0, bi0), 0.f);
        v1.x = fmaxf(fmaf(d[j][2], sc1, bi1), 0.f);
        v1.y = fmaxf(fmaf(d[j][3], sc1, bi1), 0.f);
        *reinterpret_cast<float2*>(dst + gq * 576 + pos)       = v0;
        *reinterpret_cast<float2*>(dst + (gq + 8) * 576 + pos) = v1;
    }
}

// ============================================================
// Kernel 2 (tensor cores): per (g,b,k) GEMM + BN + ReLU + avg-pool.
// fp16 2-term A split, single fp16 B. Epilogue: relu identity with
// exact linear part from hsum (round-10 scalar form).
// 13 warps; warp w processes strips w and w+13 together.
// ============================================================
__global__ __launch_bounds__(416) void k2_tc(
    const float* __restrict__ W2,
    const float* __restrict__ g2, const float* __restrict__ b2,
    const float* __restrict__ m2, const float* __restrict__ v2)
{
    const int k = blockIdx.x, b = blockIdx.y, g = blockIdx.z;

    __shared__ unsigned int Bv[8][584];   // pitch 584 (mod 32 == 8)
    __shared__ float part[16][48];
    __shared__ float hsum[16];

    const int tid = threadIdx.x;
    const float* src = g_h1 + ((g * 2 + b) * 256 + k * 16) * 576;

    if (tid < 384) {
        const int q = tid / 48, r = tid % 48;
        const float* s0p = src + (2 * q) * 576;
        const float* s1p = src + (2 * q + 1) * 576;
        float a0 = 0.f, a1 = 0.f;
#pragma unroll
        for (int n = 0; n < 12; ++n) {
            const int pos = r + 48 * n;
            float f0 = s0p[pos], f1 = s1p[pos];
            Bv[q][pos] = f2h2(f0, f1);
            a0 += f0; a1 += f1;
        }
        part[2 * q][r] = a0;
        part[2 * q + 1][r] = a1;
    }
    __syncthreads();
    if (tid < 16) {
        float s = 0.f;
#pragma unroll
        for (int j = 0; j < 48; ++j) s += part[tid][j];
        hsum[tid] = s;
    }
    __syncthreads();

    const int w    = tid >> 5;
    const int lane = tid & 31;
    const int gq   = lane >> 2;
    const int tg   = lane & 3;

    const int s0i = w;
    const int s1raw = w + 13;
    const int s1i = (s1raw < 25) ? s1raw : s0i;   // warp 12 duplicates (benign)

    const float hs0 = hsum[2 * tg];
    const float hs1 = hsum[2 * tg + 1];
    const float hs2 = hsum[2 * tg + 8];
    const float hs3 = hsum[2 * tg + 9];

    unsigned int ah[2][4], al[2][4];
    float sc[2][2], bi[2][2], bip[2][2], Sd[2][2];
    int acB[2];
    const int ss[2] = { s0i, s1i };
#pragma unroll
    for (int e = 0; e < 2; ++e) {
        acB[e] = k * 400 + ss[e] * 16;
        const int pi0 = g * 6400 + acB[e] + gq;
        const int pi1 = pi0 + 8;
        const float2* A0 = reinterpret_cast<const float2*>(W2 + (size_t)pi0 * 16);
        const float2* A1 = reinterpret_cast<const float2*>(W2 + (size_t)pi1 * 16);
        float2 p00 = A0[tg], p02 = A0[tg + 4];
        float2 p10 = A1[tg], p12 = A1[tg + 4];
        ah[e][0] = f2h2(hhi(p00.x), hhi(p00.y));
        ah[e][1] = f2h2(hhi(p10.x), hhi(p10.y));
        ah[e][2] = f2h2(hhi(p02.x), hhi(p02.y));
        ah[e][3] = f2h2(hhi(p12.x), hhi(p12.y));
        al[e][0] = f2h2(p00.x - hhi(p00.x), p00.y - hhi(p00.y));
        al[e][1] = f2h2(p10.x - hhi(p10.x), p10.y - hhi(p10.y));
        al[e][2] = f2h2(p02.x - hhi(p02.x), p02.y - hhi(p02.y));
        al[e][3] = f2h2(p12.x - hhi(p12.x), p12.y - hhi(p12.y));
        sc[e][0] = g2[pi0] * rsqrtf(v2[pi0] + EPSV);
        bi[e][0] = b2[pi0] - m2[pi0] * sc[e][0];
        sc[e][1] = g2[pi1] * rsqrtf(v2[pi1] + EPSV);
        bi[e][1] = b2[pi1] - m2[pi1] * sc[e][1];
        bip[e][0] = bi[e][0] / sc[e][0];
        bip[e][1] = bi[e][1] / sc[e][1];
        // exact linear part of the pooled sum: Sd = w . hsum (quad-partial)
        Sd[e][0] = p00.x * hs0 + p00.y * hs1 + p02.x * hs2 + p02.y * hs3;
        Sd[e][1] = p10.x * hs0 + p10.y * hs1 + p12.x * hs2 + p12.y * hs3;
    }

    float T[2][2] = {{0.f, 0.f}, {0.f, 0.f}};   // Sum |d + bi/sc|

#pragma unroll 4
    for (int nt = 0; nt < 72; ++nt) {
        const int pos = nt * 8 + gq;
        unsigned int b0 = Bv[tg][pos];
        unsigned int b1 = Bv[tg + 4][pos];

#pragma unroll
        for (int e = 0; e < 2; ++e) {
            float d0 = 0.f, d1 = 0.f, d2 = 0.f, d3 = 0.f;
            mma_f16(d0, d1, d2, d3, al[e][0], al[e][1], al[e][2], al[e][3], b0, b1);
            mma_f16(d0, d1, d2, d3, ah[e][0], ah[e][1], ah[e][2], ah[e][3], b0, b1);
            T[e][0] += fabsf(d0 + bip[e][0]) + fabsf(d1 + bip[e][0]);
            T[e][1] += fabsf(d2 + bip[e][1]) + fabsf(d3 + bip[e][1]);
        }
    }

#pragma unroll
    for (int e = 0; e < 2; ++e) {
        float t0 = T[e][0], t1 = T[e][1];
        float s0 = Sd[e][0], s1 = Sd[e][1];
        t0 += __shfl_xor_sync(0xffffffffu, t0, 1);
        t0 += __shfl_xor_sync(0xffffffffu, t0, 2);
        t1 += __shfl_xor_sync(0xffffffffu, t1, 1);
        t1 += __shfl_xor_sync(0xffffffffu, t1, 2);
        s0 += __shfl_xor_sync(0xffffffffu, s0, 1);
        s0 += __shfl_xor_sync(0xffffffffu, s0, 2);
        s1 += __shfl_xor_sync(0xffffffffu, s1, 1);
        s1 += __shfl_xor_sync(0xffffffffu, s1, 2);
        if (tg == 0) {
            float* dst = g_pooled + (g * 2 + b) * 6400;
            float S0 = fmaf(sc[e][0], s0, 576.f * bi[e][0]);
            float R0 = 0.5f * fmaf(sc[e][0], t0, S0);
            float S1 = fmaf(sc[e][1], s1, 576.f * bi[e][1]);
            float R1 = 0.5f * fmaf(sc[e][1], t1, S1);
            dst[acB[e] + gq]     = (R0 + 100.f * fmaxf(bi[e][0], 0.f)) * (1.f / 676.f);
            dst[acB[e] + gq + 8] = (R1 + 100.f * fmaxf(bi[e][1], 0.f)) * (1.f / 676.f);
        }
    }
}

// ============================================================
// Kernel 3: affinity rows. grid 32 = (i*2+b), 512 thr = 16 warps
// ============================================================
__global__ __launch_bounds__(512) void k3_aff()
{
    const int ib = blockIdx.x;
    const int i = ib >> 1;
    const int wrp = threadIdx.x >> 5, lane = threadIdx.x & 31;
    const float* base = g_pooled + ib * 6400;
    const float* pa = base + i * 400;
    const float* pb = base + wrp * 400;
    float s = 0.f;
    for (int m = lane; m < 400; m += 32) s += pa[m] * pb[m];
#pragma unroll
    for (int o = 16; o; o >>= 1) s += __shfl_xor_sync(0xffffffffu, s, o);
    if (lane == 0) g_aff[ib * 16 + wrp] = s * (1.f / 16.f);
}

// ============================================================
// Kernel 4: z = aff . h1 -> out, float4 vectorized
// grid (cg=16, q=2, i=16), 144 threads, each owns 4 positions
// ============================================================
__global__ __launch_bounds__(144) void k4_out(float* __restrict__ out)
{
    const int cg = blockIdx.x, q = blockIdx.y, i = blockIdx.z;
    __shared__ float a0[16], a1[16];
    const int tid = threadIdx.x;
    if (tid < 16)      a0[tid]      = g_aff[(i * 2 + 0) * 16 + tid];
    else if (tid < 32) a1[tid - 16] = g_aff[(i * 2 + 1) * 16 + (tid - 16)];
    __syncthreads();

    const float4* hb = reinterpret_cast<const float4*>(
        g_h1 + ((i * 2 + q) * 256 + cg) * 576) + tid;
    float4 acc0 = {0.f, 0.f, 0.f, 0.f};
    float4 acc1 = {0.f, 0.f, 0.f, 0.f};
#pragma unroll
    for (int kk = 0; kk < 16; ++kk) {
        float4 hv = hb[kk * 16 * 144];
        float w0 = a0[kk], w1 = a1[kk];
        acc0.x = fmaf(w0, hv.x, acc0.x); acc0.y = fmaf(w0, hv.y, acc0.y);
        acc0.z = fmaf(w0, hv.z, acc0.z); acc0.w = fmaf(w0, hv.w, acc0.w);
        acc1.x = fmaf(w1, hv.x, acc1.x); acc1.y = fmaf(w1, hv.y, acc1.y);
        acc1.z = fmaf(w1, hv.z, acc1.z); acc1.w = fmaf(w1, hv.w, acc1.w);
    }
    const int ch = (i * 2 + q) * 16 + cg;
    float4* o0 = reinterpret_cast<float4*>(out + (0 * 512 + ch) * 576) + tid;
    float4* o1 = reinterpret_cast<float4*>(out + (1 * 512 + ch) * 576) + tid;
    *o0 = acc0;
    *o1 = acc1;
}

// ============================================================
extern "C" void kernel_launch(void* const* d_in, const int* in_sizes, int n_in,
                              void* d_out, int out_size)
{
    const float* x  = (const float*)d_in[0];
    const float* W1 = (const float*)d_in[1];
    const float* g1 = (const float*)d_in[2];
    const float* b1 = (const float*)d_in[3];
    const float* m1 = (const float*)d_in[4];
    const float* v1 = (const float*)d_in[5];
    const float* W2 = (const float*)d_in[6];
    const float* g2 = (const float*)d_in[7];
    const float* b2 = (const float*)d_in[8];
    const float* m2 = (const float*)d_in[9];
    const float* v2 = (const float*)d_in[10];
    float* out = (float*)d_out;

    cudaFuncSetAttribute(k1_tc, cudaFuncAttributeMaxDynamicSharedMemorySize, K1_DYN);

    dim3 grid(16, 2, 16);
    k1_tc <<<grid, 288, K1_DYN>>>(x, W1, g1, b1, m1, v1);
    k2_tc <<<grid, 416>>>(W2, g2, b2, m2, v2);
    k3_aff<<<32, 512>>>();
    k4_out<<<grid, 144>>>(out);
}

// round 13
// speedup vs baseline: 1.5152x; 1.1981x over previous
#include <cuda_runtime.h>
#include <cuda_fp16.h>

#define G   16
#define Bsz 2
#define C   256
#define Cg  16
#define HW  576
#define AC  6400
#define EPSV 1e-5f

// -------- device scratch --------
__device__ float g_h1[G * Bsz * C * HW];   // 18.9 MB
__device__ float g_pooled[G * Bsz * AC];
__device__ float g_aff[G * Bsz * G];

// ---------- fp16 helpers ----------
__device__ __forceinline__ unsigned int f2h2(float lo, float hi) {
    __half2 h = __floats2half2_rn(lo, hi);
    return *reinterpret_cast<unsigned int*>(&h);
}
__device__ __forceinline__ void mma_f16(
    float& d0, float& d1, float& d2, float& d3,
    unsigned int a0, unsigned int a1, unsigned int a2, unsigned int a3,
    unsigned int b0, unsigned int b1)
{
    asm("mma.sync.aligned.m16n8k16.row.col.f32.f16.f16.f32 "
        "{%0,%1,%2,%3}, {%4,%5,%6,%7}, {%8,%9}, {%0,%1,%2,%3};"
        : "+f"(d0), "+f"(d1), "+f"(d2), "+f"(d3)
        : "r"(a0), "r"(a1), "r"(a2), "r"(a3), "r"(b0), "r"(b1));
}

// ============================================================
// Kernel 1 (tensor cores): grouped 3x3 conv + BN + ReLU -> g_h1
// Implicit GEMM over K = 9 taps x 16 ci, single fp16.
// grid (k=16, b=2, g=16), 288 threads = 9 warps.
// ============================================================
#define BPITCH 680
#define K1_DYN ((8*BPITCH + 9*128 + 32) * 4)

__global__ __launch_bounds__(288) void k1_tc(
    const float* __restrict__ x,
    const float* __restrict__ W1,
    const float* __restrict__ g1, const float* __restrict__ b1,
    const float* __restrict__ m1, const float* __restrict__ v1)
{
    const int k = blockIdx.x, b = blockIdx.y, g = blockIdx.z;
    extern __shared__ unsigned int dyn[];
    unsigned int* Bv = dyn;                 // 8 ci-pairs x BPITCH (fp16x2)
    unsigned int* Ah = Bv + 8 * BPITCH;     // [tap9][pair8][row16]
    float* scb = reinterpret_cast<float*>(Ah + 9 * 128);

    const int tid = threadIdx.x;

    for (int i = tid; i < 8 * BPITCH; i += 288) Bv[i] = 0u;

    const float* wsrc = W1 + (g * 256 + k * 16) * 144;  // [co16][ci16][tap9]
    for (int i = tid; i < 1152; i += 288) {
        int t = i / 128, rem = i % 128, p = rem / 16, r = rem % 16;
        Ah[i] = f2h2(wsrc[r * 144 + (2 * p) * 9 + t],
                     wsrc[r * 144 + (2 * p + 1) * 9 + t]);
    }
    if (tid < 16) {
        const int ch = g * 256 + k * 16 + tid;
        float sc = g1[ch] * rsqrtf(v1[ch] + EPSV);
        scb[tid] = sc;
        scb[16 + tid] = b1[ch] - m1[ch] * sc;
    }
    __syncthreads();

    const float* xs = x + (b * 256 + k * 16) * 576;
    for (int i = tid; i < 8 * 576; i += 288) {
        int q = i / 576, pos = i % 576;
        int y = pos / 24, xx = pos % 24;
        Bv[q * BPITCH + (y + 1) * 26 + (xx + 1)] =
            f2h2(xs[(2 * q) * 576 + pos], xs[(2 * q + 1) * 576 + pos]);
    }
    __syncthreads();

    const int w    = tid >> 5;
    const int lane = tid & 31;
    const int gq   = lane >> 2;
    const int tg   = lane & 3;

    float d[8][4];
#pragma unroll
    for (int j = 0; j < 8; ++j)
#pragma unroll
        for (int c = 0; c < 4; ++c) d[j][c] = 0.f;

#pragma unroll
    for (int t = 0; t < 9; ++t) {
        const int base = t * 128;
        unsigned int ah0 = Ah[base + tg * 16 + gq];
        unsigned int ah1 = Ah[base + tg * 16 + gq + 8];
        unsigned int ah2 = Ah[base + (tg + 4) * 16 + gq];
        unsigned int ah3 = Ah[base + (tg + 4) * 16 + gq + 8];
        const int ty = t / 3, tx = t % 3;

#pragma unroll
        for (int j = 0; j < 8; ++j) {
            const int nt = w * 8 + j;
            const int y = nt / 3, x0 = (nt % 3) * 8;
            const int pp = (y + ty) * 26 + x0 + gq + tx;
            unsigned int b0 = Bv[tg * BPITCH + pp];
            unsigned int b1 = Bv[(tg + 4) * BPITCH + pp];
            mma_f16(d[j][0], d[j][1], d[j][2], d[j][3], ah0, ah1, ah2, ah3, b0, b1);
        }
    }

    const float sc0 = scb[gq],     bi0 = scb[16 + gq];
    const float sc1 = scb[gq + 8], bi1 = scb[24 + gq];
    float* dst = g_h1 + ((g * 2 + b) * 256 + k * 16) * 576;
#pragma unroll
    for (int j = 0; j < 8; ++j) {
        const int nt = w * 8 + j;
        const int pos = nt * 8 + 2 * tg;
        float2 v0, v1;
        v0.x = fmaxf(fmaf(d[j][0], sc0, bi0), 0.f);
        v0.y = fmaxf(fmaf(d[j][1], sc0, bi0), 0.f);
        v1.x = fmaxf(fmaf(d[j][2], sc1, bi1), 0.f);
        v1.y = fmaxf(fmaf(d[j][3], sc1, bi1), 0.f);
        *reinterpret_cast<float2*>(dst + gq * 576 + pos)       = v0;
        *reinterpret_cast<float2*>(dst + (gq + 8) * 576 + pos) = v1;
    }
}

// ============================================================
// Kernel 2 (tensor cores): per (g,b,k) GEMM + BN + ReLU + avg-pool.
// Single fp16 A and B. Epilogue: relu identity, exact linear part
// from hsum. 13 warps; warp w processes strips w and w+13 together.
// ============================================================
__global__ __launch_bounds__(416) void k2_tc(
    const float* __restrict__ W2,
    const float* __restrict__ g2, const float* __restrict__ b2,
    const float* __restrict__ m2, const float* __restrict__ v2)
{
    const int k = blockIdx.x, b = blockIdx.y, g = blockIdx.z;

    __shared__ unsigned int Bv[8][584];   // pitch 584 (mod 32 == 8)
    __shared__ float part[16][48];
    __shared__ float hsum[16];

    const int tid = threadIdx.x;
    const float* src = g_h1 + ((g * 2 + b) * 256 + k * 16) * 576;

    if (tid < 384) {
        const int q = tid / 48, r = tid % 48;
        const float* s0p = src + (2 * q) * 576;
        const float* s1p = src + (2 * q + 1) * 576;
        float a0 = 0.f, a1 = 0.f;
#pragma unroll
        for (int n = 0; n < 12; ++n) {
            const int pos = r + 48 * n;
            float f0 = s0p[pos], f1 = s1p[pos];
            Bv[q][pos] = f2h2(f0, f1);
            a0 += f0; a1 += f1;
        }
        part[2 * q][r] = a0;
        part[2 * q + 1][r] = a1;
    }
    __syncthreads();
    if (tid < 16) {
        float s = 0.f;
#pragma unroll
        for (int j = 0; j < 48; ++j) s += part[tid][j];
        hsum[tid] = s;
    }
    __syncthreads();

    const int w    = tid >> 5;
    const int lane = tid & 31;
    const int gq   = lane >> 2;
    const int tg   = lane & 3;

    const int s0i = w;
    const int s1raw = w + 13;
    const int s1i = (s1raw < 25) ? s1raw : s0i;   // warp 12 duplicates (benign)

    const float hs0 = hsum[2 * tg];
    const float hs1 = hsum[2 * tg + 1];
    const float hs2 = hsum[2 * tg + 8];
    const float hs3 = hsum[2 * tg + 9];

    unsigned int ah[2][4];
    float sc[2][2], bi[2][2], bip[2][2], Sd[2][2];
    int acB[2];
    const int ss[2] = { s0i, s1i };
#pragma unroll
    for (int e = 0; e < 2; ++e) {
        acB[e] = k * 400 + ss[e] * 16;
        const int pi0 = g * 6400 + acB[e] + gq;
        const int pi1 = pi0 + 8;
        const float2* A0 = reinterpret_cast<const float2*>(W2 + (size_t)pi0 * 16);
        const float2* A1 = reinterpret_cast<const float2*>(W2 + (size_t)pi1 * 16);
        float2 p00 = A0[tg], p02 = A0[tg + 4];
        float2 p10 = A1[tg], p12 = A1[tg + 4];
        ah[e][0] = f2h2(p00.x, p00.y);
        ah[e][1] = f2h2(p10.x, p10.y);
        ah[e][2] = f2h2(p02.x, p02.y);
        ah[e][3] = f2h2(p12.x, p12.y);
        sc[e][0] = g2[pi0] * rsqrtf(v2[pi0] + EPSV);
        bi[e][0] = b2[pi0] - m2[pi0] * sc[e][0];
        sc[e][1] = g2[pi1] * rsqrtf(v2[pi1] + EPSV);
        bi[e][1] = b2[pi1] - m2[pi1] * sc[e][1];
        bip[e][0] = bi[e][0] / sc[e][0];
        bip[e][1] = bi[e][1] / sc[e][1];
        Sd[e][0] = p00.x * hs0 + p00.y * hs1 + p02.x * hs2 + p02.y * hs3;
        Sd[e][1] = p10.x * hs0 + p10.y * hs1 + p12.x * hs2 + p12.y * hs3;
    }

    float T[2][2] = {{0.f, 0.f}, {0.f, 0.f}};   // Sum |d + bi/sc|

#pragma unroll 4
    for (int nt = 0; nt < 72; ++nt) {
        const int pos = nt * 8 + gq;
        unsigned int b0 = Bv[tg][pos];
        unsigned int b1 = Bv[tg + 4][pos];

#pragma unroll
        for (int e = 0; e < 2; ++e) {
            float d0 = 0.f, d1 = 0.f, d2 = 0.f, d3 = 0.f;
            mma_f16(d0, d1, d2, d3, ah[e][0], ah[e][1], ah[e][2], ah[e][3], b0, b1);
            T[e][0] += fabsf(d0 + bip[e][0]) + fabsf(d1 + bip[e][0]);
            T[e][1] += fabsf(d2 + bip[e][1]) + fabsf(d3 + bip[e][1]);
        }
    }

#pragma unroll
    for (int e = 0; e < 2; ++e) {
        float t0 = T[e][0], t1 = T[e][1];
        float s0 = Sd[e][0], s1 = Sd[e][1];
        t0 += __shfl_xor_sync(0xffffffffu, t0, 1);
        t0 += __shfl_xor_sync(0xffffffffu, t0, 2);
        t1 += __shfl_xor_sync(0xffffffffu, t1, 1);
        t1 += __shfl_xor_sync(0xffffffffu, t1, 2);
        s0 += __shfl_xor_sync(0xffffffffu, s0, 1);
        s0 += __shfl_xor_sync(0xffffffffu, s0, 2);
        s1 += __shfl_xor_sync(0xffffffffu, s1, 1);
        s1 += __shfl_xor_sync(0xffffffffu, s1, 2);
        if (tg == 0) {
            float* dst = g_pooled + (g * 2 + b) * 6400;
            float S0 = fmaf(sc[e][0], s0, 576.f * bi[e][0]);
            float R0 = 0.5f * fmaf(sc[e][0], t0, S0);
            float S1 = fmaf(sc[e][1], s1, 576.f * bi[e][1]);
            float R1 = 0.5f * fmaf(sc[e][1], t1, S1);
            dst[acB[e] + gq]     = (R0 + 100.f * fmaxf(bi[e][0], 0.f)) * (1.f / 676.f);
            dst[acB[e] + gq + 8] = (R1 + 100.f * fmaxf(bi[e][1], 0.f)) * (1.f / 676.f);
        }
    }
}

// ============================================================
// Kernel 3: affinity rows. grid 32 = (i*2+b), 512 thr = 16 warps
// ============================================================
__global__ __launch_bounds__(512) void k3_aff()
{
    const int ib = blockIdx.x;
    const int i = ib >> 1;
    const int wrp = threadIdx.x >> 5, lane = threadIdx.x & 31;
    const float* base = g_pooled + ib * 6400;
    const float* pa = base + i * 400;
    const float* pb = base + wrp * 400;
    float s = 0.f;
    for (int m = lane; m < 400; m += 32) s += pa[m] * pb[m];
#pragma unroll
    for (int o = 16; o; o >>= 1) s += __shfl_xor_sync(0xffffffffu, s, o);
    if (lane == 0) g_aff[ib * 16 + wrp] = s * (1.f / 16.f);
}

// ============================================================
// Kernel 4: z = aff . h1 -> out, float2 per thread (288 threads)
// grid (cg=16, q=2, i=16)
// ============================================================
__global__ __launch_bounds__(288) void k4_out(float* __restrict__ out)
{
    const int cg = blockIdx.x, q = blockIdx.y, i = blockIdx.z;
    __shared__ float a0[16], a1[16];
    const int tid = threadIdx.x;
    if (tid < 16)      a0[tid]      = g_aff[(i * 2 + 0) * 16 + tid];
    else if (tid < 32) a1[tid - 16] = g_aff[(i * 2 + 1) * 16 + (tid - 16)];
    __syncthreads();

    const float2* hb = reinterpret_cast<const float2*>(
        g_h1 + ((i * 2 + q) * 256 + cg) * 576) + tid;
    float2 acc0 = {0.f, 0.f};
    float2 acc1 = {0.f, 0.f};
#pragma unroll
    for (int kk = 0; kk < 16; ++kk) {
        float2 hv = hb[kk * 16 * 288];
        float w0 = a0[kk], w1 = a1[kk];
        acc0.x = fmaf(w0, hv.x, acc0.x); acc0.y = fmaf(w0, hv.y, acc0.y);
        acc1.x = fmaf(w1, hv.x, acc1.x); acc1.y = fmaf(w1, hv.y, acc1.y);
    }
    const int ch = (i * 2 + q) * 16 + cg;
    float2* o0 = reinterpret_cast<float2*>(out + (0 * 512 + ch) * 576) + tid;
    float2* o1 = reinterpret_cast<float2*>(out + (1 * 512 + ch) * 576) + tid;
    *o0 = acc0;
    *o1 = acc1;
}

// ============================================================
extern "C" void kernel_launch(void* const* d_in, const int* in_sizes, int n_in,
                              void* d_out, int out_size)
{
    const float* x  = (const float*)d_in[0];
    const float* W1 = (const float*)d_in[1];
    const float* g1 = (const float*)d_in[2];
    const float* b1 = (const float*)d_in[3];
    const float* m1 = (const float*)d_in[4];
    const float* v1 = (const float*)d_in[5];
    const float* W2 = (const float*)d_in[6];
    const float* g2 = (const float*)d_in[7];
    const float* b2 = (const float*)d_in[8];
    const float* m2 = (const float*)d_in[9];
    const float* v2 = (const float*)d_in[10];
    float* out = (float*)d_out;

    cudaFuncSetAttribute(k1_tc, cudaFuncAttributeMaxDynamicSharedMemorySize, K1_DYN);

    dim3 grid(16, 2, 16);
    k1_tc <<<grid, 288, K1_DYN>>>(x, W1, g1, b1, m1, v1);
    k2_tc <<<grid, 416>>>(W2, g2, b2, m2, v2);
    k3_aff<<<32, 512>>>();
    k4_out<<<grid, 288>>>(out);
}